// round 4
// baseline (speedup 1.0000x reference)
#include <cuda_runtime.h>
#include <cstdint>

#define B    32
#define NN   2000
#define TD   384
#define E    64
#define TT   24
#define DD   16

#define BRR  64      // query rows per CTA
#define BCC  32      // kv rows per tile
#define NT   63      // ceil(NN/BCC)
#define KST  68      // k row stride (floats)
#define VST  384     // v row stride
#define PST  66      // p row stride in u64 (64 data + 2 pad)
#define OST  388     // stage row stride (floats)
#define OST4 97

// attn smem layout (floats)
#define O_Q  0                         // 64*64        = 4096
#define O_K  4096                      // 3 * 32*68    = 6528
#define O_V  10624                     // 3 * 32*384   = 36864
#define O_P  47488                     // 32*66 u64    = 4224 floats
#define O_L  51712                     // 64 floats
#define SM_FLOATS 51776
#define SM_BYTES (SM_FLOATS*4)         // 207104 B

// kernel-1 smem layout (floats)
#define K1_ROWS 64
#define W_CH    32                     // td rows per W chunk
#define N_CH    (TD / W_CH)            // 12 chunks
#define K1_XS   0                      // 64*384 = 24576
#define K1_WS   24576                  // 2 * 32*128 = 8192
#define K1_QK   32768                  // 64*128 = 8192
#define K1_MU   40960                  // 128
#define K1_RS   41088                  // 128
#define K1_SM_FLOATS 41216
#define K1_SM_BYTES (K1_SM_FLOATS*4)   // 164864 B

typedef unsigned long long u64;

// scratch (device globals: the sanctioned no-alloc path)
__device__ float g_q1[B*NN*E];   // 16 MB
__device__ float g_k1[B*NN*E];   // 16 MB

// ---------- packed f32x2 helpers ----------
__device__ __forceinline__ u64 pack2(float a, float b){
    u64 r; asm("mov.b64 %0,{%1,%2};" : "=l"(r) : "f"(a), "f"(b)); return r;
}
__device__ __forceinline__ void ffma2(u64 &d, u64 a, u64 b){
    asm("fma.rn.f32x2 %0,%1,%2,%0;" : "+l"(d) : "l"(a), "l"(b));
}
__device__ __forceinline__ float2 unpack2(u64 v){
    float2 r; asm("mov.b64 {%0,%1},%2;" : "=f"(r.x), "=f"(r.y) : "l"(v)); return r;
}
__device__ __forceinline__ unsigned smaddr(const void* p){
    return (unsigned)__cvta_generic_to_shared(p);
}
__device__ __forceinline__ void cpa16(unsigned d, const void* s){
    asm volatile("cp.async.cg.shared.global [%0],[%1],16;" :: "r"(d), "l"(s));
}

// ============================================================
// Kernel 1: q1 = LN(xf@Wq + bq), k1 = LN(xf@Wk + bk)
// 64 rows/CTA, 512 threads. grp = tid>>6: bit2 = isK, bits[0:1] = row quarter.
// Each thread: one output column x 16 rows. W staged via smem chunks (cp.async).
// ============================================================
__device__ __forceinline__ void k1_prefetch_w(float* ws, int tid, int c,
        const float* Wq, const float* Wk)
{
    if (c < N_CH) {
        float* dst = ws + (c & 1) * (W_CH * 128);
        int c0 = c * W_CH;
#pragma unroll
        for (int j = 0; j < 2; j++) {
            int idx = tid + j*512;         // 1024 float4 per chunk
            int row = idx >> 5, c4 = idx & 31;
            const float* src = (c4 < 16)
                ? (Wq + (size_t)(c0 + row)*E + c4*4)
                : (Wk + (size_t)(c0 + row)*E + (c4 - 16)*4);
            cpa16(smaddr(dst + row*128 + ((c4 < 16) ? c4*4 : 64 + (c4-16)*4)), src);
        }
    }
    asm volatile("cp.async.commit_group;");
}

__global__ __launch_bounds__(512, 1) void qk_ln_kernel(
    const float* __restrict__ x,
    const float* __restrict__ Wq, const float* __restrict__ bq,
    const float* __restrict__ Wk, const float* __restrict__ bk,
    const float* __restrict__ g0, const float* __restrict__ beta0,
    const float* __restrict__ g1, const float* __restrict__ beta1)
{
    extern __shared__ float sm1[];
    float* xs = sm1 + K1_XS;
    float* ws = sm1 + K1_WS;
    float* qk = sm1 + K1_QK;
    float* mu_sh = sm1 + K1_MU;
    float* rs_sh = sm1 + K1_RS;
    const int tid = threadIdx.x;
    const long base = (long)blockIdx.x * K1_ROWS;   // 1000 CTAs exact

    k1_prefetch_w(ws, tid, 0, Wq, Wk);
    k1_prefetch_w(ws, tid, 1, Wq, Wk);

    const float4* xp4 = (const float4*)(x + base*TD);
#pragma unroll
    for (int i = 0; i < 12; i++) ((float4*)xs)[tid + i*512] = xp4[tid + i*512];

    const int col = tid & 63;
    const int grp = tid >> 6;
    const int isK = grp >> 2;
    const int r0  = (grp & 3) * 16;
    const int wcol = isK*64 + col;

    u64 acc2[16];
#pragma unroll
    for (int r = 0; r < 16; r++) acc2[r] = 0ull;

    for (int c = 0; c < N_CH; c++) {
        const float* wb = ws + (c & 1) * (W_CH * 128);
        asm volatile("cp.async.wait_group 1;");
        __syncthreads();
#pragma unroll
        for (int i4l = 0; i4l < W_CH/4; i4l++) {
            int i4 = c*(W_CH/4) + i4l;
            float w0 = wb[(i4l*4 + 0)*128 + wcol];
            float w1 = wb[(i4l*4 + 1)*128 + wcol];
            float w2 = wb[(i4l*4 + 2)*128 + wcol];
            float w3 = wb[(i4l*4 + 3)*128 + wcol];
            u64 wa = pack2(w0, w1), wbp = pack2(w2, w3);
#pragma unroll
            for (int r = 0; r < 16; r++) {
                ulonglong2 xv = ((const ulonglong2*)(xs + (r0 + r)*TD))[i4];  // broadcast
                ffma2(acc2[r], xv.x, wa);
                ffma2(acc2[r], xv.y, wbp);
            }
        }
        __syncthreads();
        k1_prefetch_w(ws, tid, c + 2, Wq, Wk);
    }

    const float bias = isK ? bk[col] : bq[col];
#pragma unroll
    for (int r = 0; r < 16; r++) {
        float2 f = unpack2(acc2[r]);
        qk[(r0 + r)*128 + isK*64 + col] = f.x + f.y + bias;
    }
    __syncthreads();

    if (tid < 128) {
        int r = tid & 63, h = tid >> 6;
        const float* v = qk + r*128 + h*64;
        float s = 0.f, s2 = 0.f;
#pragma unroll
        for (int j = 0; j < 64; j++) { float t = v[(j + r) & 63]; s += t; s2 += t*t; }
        float mu = s * (1.f/64.f);
        float var = s2 * (1.f/64.f) - mu*mu;
        mu_sh[tid] = mu;
        rs_sh[tid] = rsqrtf(var + 1e-5f);
    }
    __syncthreads();

    const float gg = isK ? g1[col] : g0[col];
    const float bb = isK ? beta1[col] : beta0[col];
    float* __restrict__ outp = isK ? g_k1 : g_q1;
#pragma unroll
    for (int r = 0; r < 16; r++) {
        float mu = mu_sh[isK*64 + r0 + r], rs = rs_sh[isK*64 + r0 + r];
        outp[(base + r0 + r)*E + col] = (qk[(r0 + r)*128 + isK*64 + col] - mu) * rs * gg + bb;
    }
}

// ============================================================
// Kernel 2: flash attention (no running max: q,k are LN'd -> |S| <= 1.43)
// BR=64 rows/CTA, 256 threads, 1 CTA/SM.
// PV layout: rgV=tid>>6 (16 rows each), cgV=tid&63 (6 cols each) -> acc 16x3 u64.
// S layout:  warp w (8 warps) handles rows w*8..w*8+7, lane = m index.
// Triple-buffered cp.async prefetch of K/V tiles.
// ============================================================
__device__ __forceinline__ void prefetch_tile(float* sm, int tid, int t,
        const float4* k1p4, const float4* nrm4)
{
    if (t < NT) {
        int s = t - (t/3)*3;
        int m0 = t * BCC;
        float* kd = sm + O_K + s*(BCC*KST);
        float* vd = sm + O_V + s*(BCC*VST);
#pragma unroll
        for (int i = 0; i < 2; i++) {   // K: 512 float4
            int idx = tid + i*256;
            int mm = idx >> 4, j4 = idx & 15;
            int g = m0 + mm; if (g >= NN) g = NN - 1;
            cpa16(smaddr(kd + mm*KST + j4*4), k1p4 + (size_t)g*16 + j4);
        }
#pragma unroll
        for (int i = 0; i < 12; i++) {  // V: 3072 float4
            int idx = tid + i*256;
            int mm = idx / 96, c4 = idx - mm*96;
            int g = m0 + mm; if (g >= NN) g = NN - 1;
            cpa16(smaddr(vd + mm*VST + c4*4), nrm4 + (size_t)g*96 + c4);
        }
    }
    asm volatile("cp.async.commit_group;");
}

__global__ __launch_bounds__(256, 1) void attn_kernel(
    const float* __restrict__ x,
    const float* __restrict__ normal,
    const float* __restrict__ Win,
    float* __restrict__ out)
{
    extern __shared__ float sm[];
    const int tid  = threadIdx.x;
    const int b    = blockIdx.y;
    const int n0   = blockIdx.x * BRR;
    const int rgV  = tid >> 6, cgV = tid & 63, rbV = rgV*16;
    const int warp = tid >> 5, lane = tid & 31;
    const int rowS = warp * 8;

    const float4* q1p4 = (const float4*)(g_q1 + (size_t)b*NN*E);
    const float4* k1p4 = (const float4*)(g_k1 + (size_t)b*NN*E);
    const float4* nrm4 = (const float4*)normal;

    // load q tile (clamped rows; padded rows harmless, stores guarded)
#pragma unroll
    for (int i = 0; i < 4; i++) {
        int idx = tid + i*256;
        int r = idx >> 4, j4 = idx & 15;
        int g = n0 + r; if (g >= NN) g = NN - 1;
        ((float4*)(sm + O_Q))[idx] = q1p4[(size_t)g*16 + j4];
    }
    prefetch_tile(sm, tid, 0, k1p4, nrm4);
    prefetch_tile(sm, tid, 1, k1p4, nrm4);

    u64 acc[16][3];
#pragma unroll
    for (int r = 0; r < 16; r++)
#pragma unroll
        for (int c = 0; c < 3; c++) acc[r][c] = 0ull;
    float lacc[8];
#pragma unroll
    for (int r = 0; r < 8; r++) lacc[r] = 0.f;

    u64* p_u = (u64*)(sm + O_P);
    const float scale = 0.022360679774997897f;   // 1/sqrt(2000)

    for (int t = 0; t < NT; t++) {
        int s = t - (t/3)*3;
        asm volatile("cp.async.wait_group 1;");
        __syncthreads();

        // ---- S = q.k, exp, store p (duplicated pairs) ----
        {
            const ulonglong2* kk = (const ulonglong2*)(sm + O_K + s*(BCC*KST) + lane*KST);
            u64 dacc[8];
#pragma unroll
            for (int r = 0; r < 8; r++) dacc[r] = 0ull;
#pragma unroll
            for (int j2 = 0; j2 < 16; j2++) {
                ulonglong2 kv = kk[j2];
#pragma unroll
                for (int r = 0; r < 8; r++) {
                    ulonglong2 qv = ((const ulonglong2*)(sm + O_Q + (rowS + r)*E))[j2];
                    ffma2(dacc[r], qv.x, kv.x);
                    ffma2(dacc[r], qv.y, kv.y);
                }
            }
            const bool mval = (t*BCC + lane) < NN;
            u64 pp[8];
#pragma unroll
            for (int r = 0; r < 8; r++) {
                float2 f = unpack2(dacc[r]);
                float p = mval ? __expf((f.x + f.y) * scale) : 0.f;
                lacc[r] += p;
                pp[r] = pack2(p, p);
            }
            ulonglong2* ps = (ulonglong2*)(p_u + lane*PST + rowS);
            ulonglong2 w0; w0.x = pp[0]; w0.y = pp[1]; ps[0] = w0;
            ulonglong2 w1; w1.x = pp[2]; w1.y = pp[3]; ps[1] = w1;
            ulonglong2 w2; w2.x = pp[4]; w2.y = pp[5]; ps[2] = w2;
            ulonglong2 w3; w3.x = pp[6]; w3.y = pp[7]; ps[3] = w3;
        }
        __syncthreads();
        prefetch_tile(sm, tid, t + 2, k1p4, nrm4);

        // ---- PV: acc[16 rows][6 cols] += p * v ----
        {
            const float* vb = sm + O_V + s*(BCC*VST) + cgV*6;
#pragma unroll 2
            for (int m = 0; m < BCC; m++) {
                const u64* vv = (const u64*)(vb + m*VST);
                u64 v0 = vv[0], v1 = vv[1], v2 = vv[2];
                const ulonglong2* pl = (const ulonglong2*)(p_u + m*PST + rbV);  // broadcast
                u64 pr[16];
#pragma unroll
                for (int h = 0; h < 8; h++) {
                    ulonglong2 pw = pl[h];
                    pr[2*h] = pw.x; pr[2*h + 1] = pw.y;
                }
#pragma unroll
                for (int r = 0; r < 16; r++) {
                    ffma2(acc[r][0], pr[r], v0);
                    ffma2(acc[r][1], pr[r], v1);
                    ffma2(acc[r][2], pr[r], v2);
                }
            }
        }
    }

    // ---- l: warp w owns rows w*8..w*8+7; reduce over lanes ----
#pragma unroll
    for (int r = 0; r < 8; r++) {
#pragma unroll
        for (int off = 16; off; off >>= 1)
            lacc[r] += __shfl_xor_sync(0xffffffffu, lacc[r], off);
    }
    if (lane == 0) {
        float* l_s = sm + O_L;
#pragma unroll
        for (int r = 0; r < 8; r++) l_s[rowS + r] = lacc[r];
    }
    __syncthreads();   // l_s ready AND all PV reads of V buffers done

    // ---- stage data = acc / l (reuse V area, stride OST), u64 stores ----
    float* stage = sm + O_V;
    {
        const float* l_s = sm + O_L;
#pragma unroll
        for (int r = 0; r < 16; r++) {
            float inv = 1.f / l_s[rbV + r];
            float2 a0 = unpack2(acc[r][0]);
            float2 a1 = unpack2(acc[r][1]);
            float2 a2 = unpack2(acc[r][2]);
            u64* dst = (u64*)(stage + (rbV + r)*OST + cgV*6);
            dst[0] = pack2(a0.x*inv, a0.y*inv);
            dst[1] = pack2(a1.x*inv, a1.y*inv);
            dst[2] = pack2(a2.x*inv, a2.y*inv);
        }
    }
    __syncthreads();

    // ---- RPPsAtt weights (per row) ----
    float* w_s = sm + O_P;   // reuse p area (64*24 floats)
    if (tid < BRR) {
        int n = n0 + tid;
        if (n < NN) {
            const float* xl = x + ((size_t)b*NN + n)*TD + (TT - 1)*DD;
            float q16[DD];
#pragma unroll
            for (int dp = 0; dp < DD; dp++) {
                float sacc = 0.f;
#pragma unroll
                for (int d = 0; d < DD; d++) sacc += xl[d] * Win[d*DD + dp];
                q16[dp] = sacc;
            }
            const float* row = stage + tid*OST;
            float att[TT]; float mx = -1e30f;
#pragma unroll
            for (int tt2 = 0; tt2 < TT; tt2++) {
                float sacc = 0.f;
#pragma unroll
                for (int d = 0; d < DD; d++) sacc += q16[d] * row[tt2*DD + d];
                att[tt2] = sacc; mx = fmaxf(mx, sacc);
            }
            float se = 0.f;
#pragma unroll
            for (int tt2 = 0; tt2 < TT; tt2++) { float e = __expf(att[tt2] - mx); att[tt2] = e; se += e; }
            float si = 1.f / se;
#pragma unroll
            for (int tt2 = 0; tt2 < TT; tt2++) w_s[tid*TT + tt2] = att[tt2] * si;
        }
    }
    __syncthreads();

    // ---- out = data + weight[..., None] ----
    int nrows = NN - n0; if (nrows > BRR) nrows = BRR;
    float4* outp = (float4*)(out + ((size_t)b*NN + n0)*TD);
    for (int i = tid; i < nrows*96; i += 256) {
        int r = i / 96, c4 = i - r*96;
        float4 v = ((const float4*)stage)[r*OST4 + c4];
        float w = w_s[r*TT + (c4 >> 2)];
        v.x += w; v.y += w; v.z += w; v.w += w;
        outp[i] = v;
    }
}

// ============================================================
extern "C" void kernel_launch(void* const* d_in, const int* in_sizes, int n_in,
                              void* d_out, int out_size)
{
    (void)in_sizes; (void)n_in; (void)out_size;
    const float* x     = (const float*)d_in[0];
    const float* Wq    = (const float*)d_in[1];
    const float* bq    = (const float*)d_in[2];
    const float* Wk    = (const float*)d_in[3];
    const float* bk    = (const float*)d_in[4];
    const float* g0    = (const float*)d_in[5];
    const float* beta0 = (const float*)d_in[6];
    const float* g1    = (const float*)d_in[7];
    const float* beta1 = (const float*)d_in[8];
    const float* nrm   = (const float*)d_in[9];
    const float* Win   = (const float*)d_in[10];
    float* out = (float*)d_out;

    cudaFuncSetAttribute(qk_ln_kernel, cudaFuncAttributeMaxDynamicSharedMemorySize, K1_SM_BYTES);
    cudaFuncSetAttribute(attn_kernel,  cudaFuncAttributeMaxDynamicSharedMemorySize, SM_BYTES);

    qk_ln_kernel<<<(B*NN)/K1_ROWS, 512, K1_SM_BYTES>>>(x, Wq, bq, Wk, bk, g0, beta0, g1, beta1);

    dim3 grid((NN + BRR - 1)/BRR, B);
    attn_kernel<<<grid, 256, SM_BYTES>>>(x, nrm, Win, out);
}

// round 5
// speedup vs baseline: 1.0000x; 1.0000x over previous
#include <cuda_runtime.h>
#include <cstdint>

#define B    32
#define NN   2000
#define TD   384
#define E    64
#define TT   24
#define DD   16

#define BRR  64      // query rows per CTA
#define BCC  32      // kv rows per tile
#define NT   63      // ceil(NN/BCC)
#define KST  68      // k row stride (floats)
#define VST  384     // v row stride
#define PST  66      // p row stride in u64 (64 data + 2 pad)
#define OST  388     // stage row stride (floats)
#define OST4 97

// attn smem layout (floats)
#define O_Q  0                         // 64*64        = 4096
#define O_K  4096                      // 3 * 32*68    = 6528
#define O_V  10624                     // 3 * 32*384   = 36864
#define O_P  47488                     // 32*66 u64    = 4224 floats
#define O_L  51712                     // 64 floats
#define SM_FLOATS 51776
#define SM_BYTES (SM_FLOATS*4)         // 207104 B

// kernel-1 smem layout (floats)
#define K1_ROWS 64
#define W_CH    32                     // td rows per W chunk
#define N_CH    (TD / W_CH)            // 12 chunks
#define K1_XS   0                      // 64*384 = 24576
#define K1_WS   24576                  // 2 * 32*128 = 8192
#define K1_QK   32768                  // 64*128 = 8192
#define K1_MU   40960                  // 128
#define K1_RS   41088                  // 128
#define K1_SM_FLOATS 41216
#define K1_SM_BYTES (K1_SM_FLOATS*4)   // 164864 B

typedef unsigned long long u64;

// scratch (device globals: the sanctioned no-alloc path)
__device__ float g_q1[B*NN*E];   // 16 MB
__device__ float g_k1[B*NN*E];   // 16 MB

// ---------- packed f32x2 helpers ----------
__device__ __forceinline__ u64 pack2(float a, float b){
    u64 r; asm("mov.b64 %0,{%1,%2};" : "=l"(r) : "f"(a), "f"(b)); return r;
}
__device__ __forceinline__ void ffma2(u64 &d, u64 a, u64 b){
    asm("fma.rn.f32x2 %0,%1,%2,%0;" : "+l"(d) : "l"(a), "l"(b));
}
__device__ __forceinline__ float2 unpack2(u64 v){
    float2 r; asm("mov.b64 {%0,%1},%2;" : "=f"(r.x), "=f"(r.y) : "l"(v)); return r;
}
__device__ __forceinline__ unsigned smaddr(const void* p){
    return (unsigned)__cvta_generic_to_shared(p);
}
__device__ __forceinline__ void cpa16(unsigned d, const void* s){
    asm volatile("cp.async.cg.shared.global [%0],[%1],16;" :: "r"(d), "l"(s));
}

// ============================================================
// Kernel 1: q1 = LN(xf@Wq + bq), k1 = LN(xf@Wk + bk)
// 64 rows/CTA, 512 threads. grp = tid>>6: bit2 = isK, bits[0:1] = row quarter.
// Each thread: one output column x 16 rows. W staged via smem chunks (cp.async).
// ============================================================
__device__ __forceinline__ void k1_prefetch_w(float* ws, int tid, int c,
        const float* Wq, const float* Wk)
{
    if (c < N_CH) {
        float* dst = ws + (c & 1) * (W_CH * 128);
        int c0 = c * W_CH;
#pragma unroll
        for (int j = 0; j < 2; j++) {
            int idx = tid + j*512;         // 1024 float4 per chunk
            int row = idx >> 5, c4 = idx & 31;
            const float* src = (c4 < 16)
                ? (Wq + (size_t)(c0 + row)*E + c4*4)
                : (Wk + (size_t)(c0 + row)*E + (c4 - 16)*4);
            cpa16(smaddr(dst + row*128 + ((c4 < 16) ? c4*4 : 64 + (c4-16)*4)), src);
        }
    }
    asm volatile("cp.async.commit_group;");
}

__global__ __launch_bounds__(512, 1) void qk_ln_kernel(
    const float* __restrict__ x,
    const float* __restrict__ Wq, const float* __restrict__ bq,
    const float* __restrict__ Wk, const float* __restrict__ bk,
    const float* __restrict__ g0, const float* __restrict__ beta0,
    const float* __restrict__ g1, const float* __restrict__ beta1)
{
    extern __shared__ float sm1[];
    float* xs = sm1 + K1_XS;
    float* ws = sm1 + K1_WS;
    float* qk = sm1 + K1_QK;
    float* mu_sh = sm1 + K1_MU;
    float* rs_sh = sm1 + K1_RS;
    const int tid = threadIdx.x;
    const long base = (long)blockIdx.x * K1_ROWS;   // 1000 CTAs exact

    k1_prefetch_w(ws, tid, 0, Wq, Wk);
    k1_prefetch_w(ws, tid, 1, Wq, Wk);

    const float4* xp4 = (const float4*)(x + base*TD);
#pragma unroll
    for (int i = 0; i < 12; i++) ((float4*)xs)[tid + i*512] = xp4[tid + i*512];

    const int col = tid & 63;
    const int grp = tid >> 6;
    const int isK = grp >> 2;
    const int r0  = (grp & 3) * 16;
    const int wcol = isK*64 + col;

    u64 acc2[16];
#pragma unroll
    for (int r = 0; r < 16; r++) acc2[r] = 0ull;

    for (int c = 0; c < N_CH; c++) {
        const float* wb = ws + (c & 1) * (W_CH * 128);
        asm volatile("cp.async.wait_group 1;");
        __syncthreads();
#pragma unroll
        for (int i4l = 0; i4l < W_CH/4; i4l++) {
            int i4 = c*(W_CH/4) + i4l;
            float w0 = wb[(i4l*4 + 0)*128 + wcol];
            float w1 = wb[(i4l*4 + 1)*128 + wcol];
            float w2 = wb[(i4l*4 + 2)*128 + wcol];
            float w3 = wb[(i4l*4 + 3)*128 + wcol];
            u64 wa = pack2(w0, w1), wbp = pack2(w2, w3);
#pragma unroll
            for (int r = 0; r < 16; r++) {
                ulonglong2 xv = ((const ulonglong2*)(xs + (r0 + r)*TD))[i4];  // broadcast
                ffma2(acc2[r], xv.x, wa);
                ffma2(acc2[r], xv.y, wbp);
            }
        }
        __syncthreads();
        k1_prefetch_w(ws, tid, c + 2, Wq, Wk);
    }

    const float bias = isK ? bk[col] : bq[col];
#pragma unroll
    for (int r = 0; r < 16; r++) {
        float2 f = unpack2(acc2[r]);
        qk[(r0 + r)*128 + isK*64 + col] = f.x + f.y + bias;
    }
    __syncthreads();

    if (tid < 128) {
        int r = tid & 63, h = tid >> 6;
        const float* v = qk + r*128 + h*64;
        float s = 0.f, s2 = 0.f;
#pragma unroll
        for (int j = 0; j < 64; j++) { float t = v[(j + r) & 63]; s += t; s2 += t*t; }
        float mu = s * (1.f/64.f);
        float var = s2 * (1.f/64.f) - mu*mu;
        mu_sh[tid] = mu;
        rs_sh[tid] = rsqrtf(var + 1e-5f);
    }
    __syncthreads();

    const float gg = isK ? g1[col] : g0[col];
    const float bb = isK ? beta1[col] : beta0[col];
    float* __restrict__ outp = isK ? g_k1 : g_q1;
#pragma unroll
    for (int r = 0; r < 16; r++) {
        float mu = mu_sh[isK*64 + r0 + r], rs = rs_sh[isK*64 + r0 + r];
        outp[(base + r0 + r)*E + col] = (qk[(r0 + r)*128 + isK*64 + col] - mu) * rs * gg + bb;
    }
}

// ============================================================
// Kernel 2: flash attention (no running max: q,k are LN'd -> |S| <= 1.43)
// BR=64 rows/CTA, 256 threads, 1 CTA/SM.
// PV layout: rgV=tid>>6 (16 rows each), cgV=tid&63 (6 cols each) -> acc 16x3 u64.
// S layout:  warp w (8 warps) handles rows w*8..w*8+7, lane = m index.
// Triple-buffered cp.async prefetch of K/V tiles.
// ============================================================
__device__ __forceinline__ void prefetch_tile(float* sm, int tid, int t,
        const float4* k1p4, const float4* nrm4)
{
    if (t < NT) {
        int s = t - (t/3)*3;
        int m0 = t * BCC;
        float* kd = sm + O_K + s*(BCC*KST);
        float* vd = sm + O_V + s*(BCC*VST);
#pragma unroll
        for (int i = 0; i < 2; i++) {   // K: 512 float4
            int idx = tid + i*256;
            int mm = idx >> 4, j4 = idx & 15;
            int g = m0 + mm; if (g >= NN) g = NN - 1;
            cpa16(smaddr(kd + mm*KST + j4*4), k1p4 + (size_t)g*16 + j4);
        }
#pragma unroll
        for (int i = 0; i < 12; i++) {  // V: 3072 float4
            int idx = tid + i*256;
            int mm = idx / 96, c4 = idx - mm*96;
            int g = m0 + mm; if (g >= NN) g = NN - 1;
            cpa16(smaddr(vd + mm*VST + c4*4), nrm4 + (size_t)g*96 + c4);
        }
    }
    asm volatile("cp.async.commit_group;");
}

__global__ __launch_bounds__(256, 1) void attn_kernel(
    const float* __restrict__ x,
    const float* __restrict__ normal,
    const float* __restrict__ Win,
    float* __restrict__ out)
{
    extern __shared__ float sm[];
    const int tid  = threadIdx.x;
    const int b    = blockIdx.y;
    const int n0   = blockIdx.x * BRR;
    const int rgV  = tid >> 6, cgV = tid & 63, rbV = rgV*16;
    const int warp = tid >> 5, lane = tid & 31;
    const int rowS = warp * 8;

    const float4* q1p4 = (const float4*)(g_q1 + (size_t)b*NN*E);
    const float4* k1p4 = (const float4*)(g_k1 + (size_t)b*NN*E);
    const float4* nrm4 = (const float4*)normal;

    // load q tile (clamped rows; padded rows harmless, stores guarded)
#pragma unroll
    for (int i = 0; i < 4; i++) {
        int idx = tid + i*256;
        int r = idx >> 4, j4 = idx & 15;
        int g = n0 + r; if (g >= NN) g = NN - 1;
        ((float4*)(sm + O_Q))[idx] = q1p4[(size_t)g*16 + j4];
    }
    prefetch_tile(sm, tid, 0, k1p4, nrm4);
    prefetch_tile(sm, tid, 1, k1p4, nrm4);

    u64 acc[16][3];
#pragma unroll
    for (int r = 0; r < 16; r++)
#pragma unroll
        for (int c = 0; c < 3; c++) acc[r][c] = 0ull;
    float lacc[8];
#pragma unroll
    for (int r = 0; r < 8; r++) lacc[r] = 0.f;

    u64* p_u = (u64*)(sm + O_P);
    const float scale = 0.022360679774997897f;   // 1/sqrt(2000)

    for (int t = 0; t < NT; t++) {
        int s = t - (t/3)*3;
        asm volatile("cp.async.wait_group 1;");
        __syncthreads();

        // ---- S = q.k, exp, store p (duplicated pairs) ----
        {
            const ulonglong2* kk = (const ulonglong2*)(sm + O_K + s*(BCC*KST) + lane*KST);
            u64 dacc[8];
#pragma unroll
            for (int r = 0; r < 8; r++) dacc[r] = 0ull;
#pragma unroll
            for (int j2 = 0; j2 < 16; j2++) {
                ulonglong2 kv = kk[j2];
#pragma unroll
                for (int r = 0; r < 8; r++) {
                    ulonglong2 qv = ((const ulonglong2*)(sm + O_Q + (rowS + r)*E))[j2];
                    ffma2(dacc[r], qv.x, kv.x);
                    ffma2(dacc[r], qv.y, kv.y);
                }
            }
            const bool mval = (t*BCC + lane) < NN;
            u64 pp[8];
#pragma unroll
            for (int r = 0; r < 8; r++) {
                float2 f = unpack2(dacc[r]);
                float p = mval ? __expf((f.x + f.y) * scale) : 0.f;
                lacc[r] += p;
                pp[r] = pack2(p, p);
            }
            ulonglong2* ps = (ulonglong2*)(p_u + lane*PST + rowS);
            ulonglong2 w0; w0.x = pp[0]; w0.y = pp[1]; ps[0] = w0;
            ulonglong2 w1; w1.x = pp[2]; w1.y = pp[3]; ps[1] = w1;
            ulonglong2 w2; w2.x = pp[4]; w2.y = pp[5]; ps[2] = w2;
            ulonglong2 w3; w3.x = pp[6]; w3.y = pp[7]; ps[3] = w3;
        }
        __syncthreads();
        prefetch_tile(sm, tid, t + 2, k1p4, nrm4);

        // ---- PV: acc[16 rows][6 cols] += p * v ----
        {
            const float* vb = sm + O_V + s*(BCC*VST) + cgV*6;
#pragma unroll 2
            for (int m = 0; m < BCC; m++) {
                const u64* vv = (const u64*)(vb + m*VST);
                u64 v0 = vv[0], v1 = vv[1], v2 = vv[2];
                const ulonglong2* pl = (const ulonglong2*)(p_u + m*PST + rbV);  // broadcast
                u64 pr[16];
#pragma unroll
                for (int h = 0; h < 8; h++) {
                    ulonglong2 pw = pl[h];
                    pr[2*h] = pw.x; pr[2*h + 1] = pw.y;
                }
#pragma unroll
                for (int r = 0; r < 16; r++) {
                    ffma2(acc[r][0], pr[r], v0);
                    ffma2(acc[r][1], pr[r], v1);
                    ffma2(acc[r][2], pr[r], v2);
                }
            }
        }
    }

    // ---- l: warp w owns rows w*8..w*8+7; reduce over lanes ----
#pragma unroll
    for (int r = 0; r < 8; r++) {
#pragma unroll
        for (int off = 16; off; off >>= 1)
            lacc[r] += __shfl_xor_sync(0xffffffffu, lacc[r], off);
    }
    if (lane == 0) {
        float* l_s = sm + O_L;
#pragma unroll
        for (int r = 0; r < 8; r++) l_s[rowS + r] = lacc[r];
    }
    __syncthreads();   // l_s ready AND all PV reads of V buffers done

    // ---- stage data = acc / l (reuse V area, stride OST), u64 stores ----
    float* stage = sm + O_V;
    {
        const float* l_s = sm + O_L;
#pragma unroll
        for (int r = 0; r < 16; r++) {
            float inv = 1.f / l_s[rbV + r];
            float2 a0 = unpack2(acc[r][0]);
            float2 a1 = unpack2(acc[r][1]);
            float2 a2 = unpack2(acc[r][2]);
            u64* dst = (u64*)(stage + (rbV + r)*OST + cgV*6);
            dst[0] = pack2(a0.x*inv, a0.y*inv);
            dst[1] = pack2(a1.x*inv, a1.y*inv);
            dst[2] = pack2(a2.x*inv, a2.y*inv);
        }
    }
    __syncthreads();

    // ---- RPPsAtt weights (per row) ----
    float* w_s = sm + O_P;   // reuse p area (64*24 floats)
    if (tid < BRR) {
        int n = n0 + tid;
        if (n < NN) {
            const float* xl = x + ((size_t)b*NN + n)*TD + (TT - 1)*DD;
            float q16[DD];
#pragma unroll
            for (int dp = 0; dp < DD; dp++) {
                float sacc = 0.f;
#pragma unroll
                for (int d = 0; d < DD; d++) sacc += xl[d] * Win[d*DD + dp];
                q16[dp] = sacc;
            }
            const float* row = stage + tid*OST;
            float att[TT]; float mx = -1e30f;
#pragma unroll
            for (int tt2 = 0; tt2 < TT; tt2++) {
                float sacc = 0.f;
#pragma unroll
                for (int d = 0; d < DD; d++) sacc += q16[d] * row[tt2*DD + d];
                att[tt2] = sacc; mx = fmaxf(mx, sacc);
            }
            float se = 0.f;
#pragma unroll
            for (int tt2 = 0; tt2 < TT; tt2++) { float e = __expf(att[tt2] - mx); att[tt2] = e; se += e; }
            float si = 1.f / se;
#pragma unroll
            for (int tt2 = 0; tt2 < TT; tt2++) w_s[tid*TT + tt2] = att[tt2] * si;
        }
    }
    __syncthreads();

    // ---- out = data + weight[..., None] ----
    int nrows = NN - n0; if (nrows > BRR) nrows = BRR;
    float4* outp = (float4*)(out + ((size_t)b*NN + n0)*TD);
    for (int i = tid; i < nrows*96; i += 256) {
        int r = i / 96, c4 = i - r*96;
        float4 v = ((const float4*)stage)[r*OST4 + c4];
        float w = w_s[r*TT + (c4 >> 2)];
        v.x += w; v.y += w; v.z += w; v.w += w;
        outp[i] = v;
    }
}

// ============================================================
extern "C" void kernel_launch(void* const* d_in, const int* in_sizes, int n_in,
                              void* d_out, int out_size)
{
    (void)in_sizes; (void)n_in; (void)out_size;
    const float* x     = (const float*)d_in[0];
    const float* Wq    = (const float*)d_in[1];
    const float* bq    = (const float*)d_in[2];
    const float* Wk    = (const float*)d_in[3];
    const float* bk    = (const float*)d_in[4];
    const float* g0    = (const float*)d_in[5];
    const float* beta0 = (const float*)d_in[6];
    const float* g1    = (const float*)d_in[7];
    const float* beta1 = (const float*)d_in[8];
    const float* nrm   = (const float*)d_in[9];
    const float* Win   = (const float*)d_in[10];
    float* out = (float*)d_out;

    cudaFuncSetAttribute(qk_ln_kernel, cudaFuncAttributeMaxDynamicSharedMemorySize, K1_SM_BYTES);
    cudaFuncSetAttribute(attn_kernel,  cudaFuncAttributeMaxDynamicSharedMemorySize, SM_BYTES);

    qk_ln_kernel<<<(B*NN)/K1_ROWS, 512, K1_SM_BYTES>>>(x, Wq, bq, Wk, bk, g0, beta0, g1, beta1);

    dim3 grid((NN + BRR - 1)/BRR, B);
    attn_kernel<<<grid, 256, SM_BYTES>>>(x, nrm, Win, out);
}

// round 7
// speedup vs baseline: 2.1157x; 2.1156x over previous
#include <cuda_runtime.h>
#include <cuda_bf16.h>
#include <cstdint>

#define B    32
#define NN   2000
#define TD   384
#define E    64
#define TT   24
#define DD   16
#define NNP  2048

#define BR   64
#define BC   32
#define NTK  63

// ---- attn smem byte layout
#define OFF_K  0           // 2 stages x (2 splits x 32 rows x 144B) = 18432
#define KTILE  9216
#define KSPLIT 4608
#define OFF_V  18432       // 2 stages x (2 splits x 384 rows x 80B) = 122880
#define VTILE  61440
#define VSPLIT 30720
#define OFF_PH 141312      // 64 x 80B
#define OFF_PL 146432
#define OFF_L  151552      // 128 floats
#define SMEM_ATT 152064
#define OST 392            // epilogue stage stride (floats), reuses OFF_V area

typedef unsigned long long u64;

__device__ __align__(16) __nv_bfloat16 g_qh[B*NN*E];
__device__ __align__(16) __nv_bfloat16 g_ql[B*NN*E];
__device__ __align__(16) __nv_bfloat16 g_kh[B*NN*E];
__device__ __align__(16) __nv_bfloat16 g_kl[B*NN*E];
__device__ __align__(16) __nv_bfloat16 g_vth[TD*NNP];
__device__ __align__(16) __nv_bfloat16 g_vtl[TD*NNP];

// =================== helpers ===================
__device__ __forceinline__ uint32_t cvta_s(const void* p){
    return (uint32_t)__cvta_generic_to_shared(p);
}
__device__ __forceinline__ void cpa16(uint32_t d, const void* s){
    asm volatile("cp.async.cg.shared.global [%0],[%1],16;" :: "r"(d), "l"(s));
}
#define CP_COMMIT() asm volatile("cp.async.commit_group;")

__device__ __forceinline__ void mma16816(float* d, const uint32_t* a, const uint32_t* b){
    asm volatile("mma.sync.aligned.m16n8k16.row.col.f32.bf16.bf16.f32 "
        "{%0,%1,%2,%3},{%4,%5,%6,%7},{%8,%9},{%0,%1,%2,%3};"
        : "+f"(d[0]), "+f"(d[1]), "+f"(d[2]), "+f"(d[3])
        : "r"(a[0]), "r"(a[1]), "r"(a[2]), "r"(a[3]), "r"(b[0]), "r"(b[1]));
}

__device__ __forceinline__ float fexp(float x){   // valid |x| <= ~3
    float t = x * 1.4426950408889634f;
    float c = t + 12582912.f;
    int k = __float_as_int(c) - 0x4B400000;
    float f = t - (c - 12582912.f);
    float z = f * 0.6931471805599453f;
    float p = fmaf(z, 0.0083333333f, 0.0416666667f);
    p = fmaf(p, z, 0.1666666667f);
    p = fmaf(p, z, 0.5f);
    p = fmaf(p, z, 1.0f);
    p = fmaf(p, z, 1.0f);
    return __int_as_float(__float_as_int(p) + (k << 23));
}
__device__ __forceinline__ int imin(int a, int b){ return a < b ? a : b; }
__device__ __forceinline__ uint32_t pkbf(float a, float b){
    __nv_bfloat16 h0 = __float2bfloat16(a), h1 = __float2bfloat16(b);
    return (uint32_t)__bfloat16_as_ushort(h0) | ((uint32_t)__bfloat16_as_ushort(h1) << 16);
}
__device__ __forceinline__ u64 pk2(float a, float b){
    u64 r; asm("mov.b64 %0,{%1,%2};" : "=l"(r) : "f"(a), "f"(b)); return r;
}
__device__ __forceinline__ void ff2(u64 &d, u64 a, u64 b){
    asm("fma.rn.f32x2 %0,%1,%2,%0;" : "+l"(d) : "l"(a), "l"(b));
}
__device__ __forceinline__ float2 up2(u64 v){
    float2 r; asm("mov.b64 {%0,%1},%2;" : "=f"(r.x), "=f"(r.y) : "l"(v)); return r;
}

// ============================================================
// prep: V transposed [col][NNP kv] + bf16 hi/lo split
// ============================================================
__global__ __launch_bounds__(256) void prep_vt(const float* __restrict__ normal){
    int idx = blockIdx.x*256 + threadIdx.x;
    if (idx < TD*NNP){
        int n = idx >> 11, kv = idx & (NNP-1);
        float v = (kv < NN) ? normal[(size_t)kv*TD + n] : 0.f;
        __nv_bfloat16 h = __float2bfloat16(v);
        g_vth[idx] = h;
        g_vtl[idx] = __float2bfloat16(v - __bfloat162float(h));
    }
}

// ============================================================
// Kernel 1: q1/k1 = LN(xf@W + b) -> bf16 hi/lo splits
// ============================================================
#define K1_ROWS 64
#define W_CH 32
#define N_CH (TD / W_CH)
#define K1_XS 0
#define K1_WS 24576
#define K1_QK 32768
#define K1_MU 40960
#define K1_RS 41088
#define K1_SM_BYTES (41216*4)

__device__ __forceinline__ void k1_prefetch_w(float* ws, int tid, int c,
        const float* Wq, const float* Wk)
{
    if (c < N_CH) {
        float* dst = ws + (c & 1) * (W_CH * 128);
        int c0 = c * W_CH;
#pragma unroll
        for (int j = 0; j < 2; j++) {
            int idx = tid + j*512;
            int row = idx >> 5, c4 = idx & 31;
            const float* src = (c4 < 16)
                ? (Wq + (size_t)(c0 + row)*E + c4*4)
                : (Wk + (size_t)(c0 + row)*E + (c4 - 16)*4);
            cpa16(cvta_s(dst + row*128 + ((c4 < 16) ? c4*4 : 64 + (c4-16)*4)), src);
        }
    }
    CP_COMMIT();
}

__global__ __launch_bounds__(512, 1) void qk_ln_kernel(
    const float* __restrict__ x,
    const float* __restrict__ Wq, const float* __restrict__ bq,
    const float* __restrict__ Wk, const float* __restrict__ bk,
    const float* __restrict__ g0, const float* __restrict__ beta0,
    const float* __restrict__ g1, const float* __restrict__ beta1)
{
    extern __shared__ float sm1[];
    float* xs = sm1 + K1_XS;
    float* ws = sm1 + K1_WS;
    float* qk = sm1 + K1_QK;
    float* mu_sh = sm1 + K1_MU;
    float* rs_sh = sm1 + K1_RS;
    const int tid = threadIdx.x;
    const long base = (long)blockIdx.x * K1_ROWS;

    k1_prefetch_w(ws, tid, 0, Wq, Wk);
    k1_prefetch_w(ws, tid, 1, Wq, Wk);

    const float4* xp4 = (const float4*)(x + base*TD);
#pragma unroll
    for (int i = 0; i < 12; i++) ((float4*)xs)[tid + i*512] = xp4[tid + i*512];

    const int col = tid & 63;
    const int grp = tid >> 6;
    const int isK = grp >> 2;
    const int r0  = (grp & 3) * 16;
    const int wcol = isK*64 + col;

    u64 acc2[16];
#pragma unroll
    for (int r = 0; r < 16; r++) acc2[r] = 0ull;

    for (int c = 0; c < N_CH; c++) {
        const float* wb = ws + (c & 1) * (W_CH * 128);
        asm volatile("cp.async.wait_group 1;");
        __syncthreads();
#pragma unroll
        for (int i4l = 0; i4l < W_CH/4; i4l++) {
            int i4 = c*(W_CH/4) + i4l;
            u64 wa = pk2(wb[(i4l*4+0)*128+wcol], wb[(i4l*4+1)*128+wcol]);
            u64 wbp = pk2(wb[(i4l*4+2)*128+wcol], wb[(i4l*4+3)*128+wcol]);
#pragma unroll
            for (int r = 0; r < 16; r++) {
                ulonglong2 xv = ((const ulonglong2*)(xs + (r0 + r)*TD))[i4];
                ff2(acc2[r], xv.x, wa);
                ff2(acc2[r], xv.y, wbp);
            }
        }
        __syncthreads();
        k1_prefetch_w(ws, tid, c + 2, Wq, Wk);
    }

    const float bias = isK ? bk[col] : bq[col];
#pragma unroll
    for (int r = 0; r < 16; r++) {
        float2 f = up2(acc2[r]);
        qk[(r0 + r)*128 + isK*64 + col] = f.x + f.y + bias;
    }
    __syncthreads();

    if (tid < 128) {
        int r = tid & 63, h = tid >> 6;
        const float* v = qk + r*128 + h*64;
        float s = 0.f, s2 = 0.f;
#pragma unroll
        for (int j = 0; j < 64; j++) { float t = v[(j + r) & 63]; s += t; s2 += t*t; }
        float mu = s * (1.f/64.f);
        mu_sh[tid] = mu;
        rs_sh[tid] = rsqrtf(s2*(1.f/64.f) - mu*mu + 1e-5f);
    }
    __syncthreads();

    const float gg = isK ? g1[col] : g0[col];
    const float bb = isK ? beta1[col] : beta0[col];
    __nv_bfloat16* __restrict__ oh = isK ? g_kh : g_qh;
    __nv_bfloat16* __restrict__ ol = isK ? g_kl : g_ql;
#pragma unroll
    for (int r = 0; r < 16; r++) {
        float mu = mu_sh[isK*64 + r0 + r], rs = rs_sh[isK*64 + r0 + r];
        float val = (qk[(r0 + r)*128 + isK*64 + col] - mu) * rs * gg + bb;
        __nv_bfloat16 h = __float2bfloat16(val);
        size_t o = (size_t)(base + r0 + r)*E + col;
        oh[o] = h;
        ol[o] = __float2bfloat16(val - __bfloat162float(h));
    }
}

// ============================================================
// Kernel 2: warp-level bf16 mma.sync flash attention (hi/lo split)
// 256 threads = 8 warps: (rg = wid>>1) x (cg = wid&1)
//   S:  warp -> rows rg*16..+15, kv cols cg*16..+15 (2 n-tiles)
//   PV: warp -> rows rg*16..+15, out cols cg*192..+191 (24 n-tiles)
// ============================================================
__device__ __forceinline__ void att_prefetch(char* smem, int tid, int t, int b){
    if (t < NTK){
        int st = t & 1;
#pragma unroll
        for (int j = 0; j < 2; j++){            // K: 512 chunks
            int c = tid + j*256;
            int split = c >> 8, rem = c & 255;
            int kv = rem >> 3, ch = rem & 7;
            int g = imin(t*BC + kv, NN-1);
            const __nv_bfloat16* src = (split ? g_kl : g_kh) + ((size_t)b*NN + g)*E + ch*8;
            cpa16(cvta_s(smem + OFF_K + st*KTILE + split*KSPLIT + kv*144 + ch*16), src);
        }
#pragma unroll
        for (int j = 0; j < 12; j++){           // V: 3072 chunks
            int c = tid + j*256;
            int split = (c >= 1536) ? 1 : 0;
            int rem = c - split*1536;
            int col = rem >> 2, ch = rem & 3;
            const __nv_bfloat16* src = (split ? g_vtl : g_vth) + (size_t)col*NNP + t*BC + ch*8;
            cpa16(cvta_s(smem + OFF_V + st*VTILE + split*VSPLIT + col*80 + ch*16), src);
        }
    }
    CP_COMMIT();
}

__global__ __launch_bounds__(256, 1) void attn_mma(
    const float* __restrict__ x,
    const float* __restrict__ Win,
    float* __restrict__ out)
{
    extern __shared__ char smem[];
    const int tid = threadIdx.x;
    const int wid = tid >> 5, lane = tid & 31;
    const int gid = lane >> 2, tig = lane & 3;
    const int rg = wid >> 1, cg = wid & 1;
    const int b = blockIdx.y;
    const int n0 = blockIdx.x * BR;
    const int r0 = rg * 16;
    const float scale = 0.022360679774997897f;   // 1/sqrt(2000)

    // ---- Q fragments: hoisted into registers for the whole kernel
    uint32_t aqh[4][4], aql[4][4];
    {
        int nA = imin(n0 + r0 + gid, NN-1);
        int nB = imin(n0 + r0 + gid + 8, NN-1);
        const uint32_t* qh = (const uint32_t*)(g_qh + (size_t)b*NN*E);
        const uint32_t* ql = (const uint32_t*)(g_ql + (size_t)b*NN*E);
#pragma unroll
        for (int ks = 0; ks < 4; ks++){
            int c0 = ks*8 + tig;
            aqh[ks][0] = qh[nA*32 + c0];     aqh[ks][1] = qh[nB*32 + c0];
            aqh[ks][2] = qh[nA*32 + c0 + 4]; aqh[ks][3] = qh[nB*32 + c0 + 4];
            aql[ks][0] = ql[nA*32 + c0];     aql[ks][1] = ql[nB*32 + c0];
            aql[ks][2] = ql[nA*32 + c0 + 4]; aql[ks][3] = ql[nB*32 + c0 + 4];
        }
    }

    att_prefetch(smem, tid, 0, b);
    att_prefetch(smem, tid, 1, b);

    float dacc[24][4];
#pragma unroll
    for (int nt = 0; nt < 24; nt++)
#pragma unroll
        for (int c = 0; c < 4; c++) dacc[nt][c] = 0.f;
    float lA = 0.f, lB = 0.f;

    uint32_t* ph = (uint32_t*)(smem + OFF_PH);
    uint32_t* pl = (uint32_t*)(smem + OFF_PL);

    for (int t = 0; t < NTK; t++){
        int st = t & 1;
        asm volatile("cp.async.wait_group 1;");
        __syncthreads();

        // ---- S = Qh*Kh + Qh*Kl + Ql*Kh (per warp: 2 n-tiles)
        float sacc[2][4];
#pragma unroll
        for (int nt = 0; nt < 2; nt++)
#pragma unroll
            for (int c = 0; c < 4; c++) sacc[nt][c] = 0.f;
        {
            const uint32_t* kh = (const uint32_t*)(smem + OFF_K + st*KTILE);
            const uint32_t* kl = (const uint32_t*)(smem + OFF_K + st*KTILE + KSPLIT);
#pragma unroll
            for (int nt = 0; nt < 2; nt++){
                int base = (cg*16 + nt*8 + gid) * 36;
#pragma unroll
                for (int ks = 0; ks < 4; ks++){
                    uint32_t bh[2] = { kh[base + ks*8 + tig], kh[base + ks*8 + tig + 4] };
                    uint32_t bl[2] = { kl[base + ks*8 + tig], kl[base + ks*8 + tig + 4] };
                    mma16816(sacc[nt], aqh[ks], bh);
                    mma16816(sacc[nt], aqh[ks], bl);
                    mma16816(sacc[nt], aql[ks], bh);
                }
            }
        }

        // ---- exp + split + store P hi/lo
#pragma unroll
        for (int nt = 0; nt < 2; nt++){
            int colg = t*BC + cg*16 + nt*8 + tig*2;
            bool m0 = colg < NN, m1 = (colg + 1) < NN;
            float p0 = m0 ? fexp(sacc[nt][0]*scale) : 0.f;
            float p1 = m1 ? fexp(sacc[nt][1]*scale) : 0.f;
            float p2 = m0 ? fexp(sacc[nt][2]*scale) : 0.f;
            float p3 = m1 ? fexp(sacc[nt][3]*scale) : 0.f;
            lA += p0 + p1; lB += p2 + p3;
            float h0 = __bfloat162float(__float2bfloat16(p0));
            float h1 = __bfloat162float(__float2bfloat16(p1));
            float h2 = __bfloat162float(__float2bfloat16(p2));
            float h3 = __bfloat162float(__float2bfloat16(p3));
            int wa = (r0 + gid)*20 + cg*8 + nt*4 + tig;
            int wb = (r0 + gid + 8)*20 + cg*8 + nt*4 + tig;
            ph[wa] = pkbf(h0, h1);
            ph[wb] = pkbf(h2, h3);
            pl[wa] = pkbf(p0 - h0, p1 - h1);
            pl[wb] = pkbf(p2 - h2, p3 - h3);
        }
        __syncthreads();

        // ---- PV: dacc += Ph*Vh + Ph*Vl + Pl*Vh (24 n-tiles x 2 k-steps)
        {
            const uint32_t* vh = (const uint32_t*)(smem + OFF_V + st*VTILE);
            const uint32_t* vl = (const uint32_t*)(smem + OFF_V + st*VTILE + VSPLIT);
#pragma unroll
            for (int ks = 0; ks < 2; ks++){
                int ra = (r0 + gid)*20 + ks*8 + tig;
                int rb = (r0 + gid + 8)*20 + ks*8 + tig;
                uint32_t pah[4] = { ph[ra], ph[rb], ph[ra+4], ph[rb+4] };
                uint32_t pal[4] = { pl[ra], pl[rb], pl[ra+4], pl[rb+4] };
#pragma unroll
                for (int nt = 0; nt < 24; nt++){
                    int vb = (cg*192 + nt*8 + gid)*20 + ks*8 + tig;
                    uint32_t bh[2] = { vh[vb], vh[vb+4] };
                    uint32_t bl[2] = { vl[vb], vl[vb+4] };
                    mma16816(dacc[nt], pah, bh);
                    mma16816(dacc[nt], pah, bl);
                    mma16816(dacc[nt], pal, bh);
                }
            }
        }
        __syncthreads();
        att_prefetch(smem, tid, t + 2, b);
    }

    // ---- l reduction (rows r0+gid, r0+gid+8; partials per cg)
    lA += __shfl_xor_sync(0xffffffffu, lA, 1);
    lA += __shfl_xor_sync(0xffffffffu, lA, 2);
    lB += __shfl_xor_sync(0xffffffffu, lB, 1);
    lB += __shfl_xor_sync(0xffffffffu, lB, 2);
    float* l_s = (float*)(smem + OFF_L);
    if (tig == 0){
        l_s[cg*64 + r0 + gid]     = lA;
        l_s[cg*64 + r0 + gid + 8] = lB;
    }
    __syncthreads();
    float invA = 1.f / (l_s[r0 + gid]     + l_s[64 + r0 + gid]);
    float invB = 1.f / (l_s[r0 + gid + 8] + l_s[64 + r0 + gid + 8]);

    // ---- stage data = dacc / l into OFF_V area (stride OST)
    float* stage = (float*)(smem + OFF_V);
#pragma unroll
    for (int nt = 0; nt < 24; nt++){
        int col = cg*192 + nt*8 + tig*2;
        float* sa = stage + (r0 + gid)*OST + col;
        sa[0] = dacc[nt][0]*invA; sa[1] = dacc[nt][1]*invA;
        float* sb = stage + (r0 + gid + 8)*OST + col;
        sb[0] = dacc[nt][2]*invB; sb[1] = dacc[nt][3]*invB;
    }
    __syncthreads();

    // ---- RPPsAtt weights per row
    float* w_s = (float*)(smem + OFF_PH);   // 64*24 floats
    if (tid < BR){
        int n = n0 + tid;
        if (n < NN){
            const float* xl = x + ((size_t)b*NN + n)*TD + (TT - 1)*DD;
            float q16[DD];
#pragma unroll
            for (int dp = 0; dp < DD; dp++){
                float s = 0.f;
#pragma unroll
                for (int d = 0; d < DD; d++) s = fmaf(xl[d], Win[d*DD + dp], s);
                q16[dp] = s;
            }
            const float* row = stage + tid*OST;
            float att[TT]; float mx = -1e30f;
#pragma unroll
            for (int t2 = 0; t2 < TT; t2++){
                float s = 0.f;
#pragma unroll
                for (int d = 0; d < DD; d++) s = fmaf(q16[d], row[t2*DD + d], s);
                att[t2] = s; mx = fmaxf(mx, s);
            }
            float se = 0.f;
#pragma unroll
            for (int t2 = 0; t2 < TT; t2++){ float e = __expf(att[t2] - mx); att[t2] = e; se += e; }
            float si = 1.f / se;
#pragma unroll
            for (int t2 = 0; t2 < TT; t2++) w_s[tid*TT + t2] = att[t2] * si;
        }
    }
    __syncthreads();

    // ---- out = data + weight[..., None]
    int nrows = NN - n0; if (nrows > BR) nrows = BR;
    float4* outp = (float4*)(out + ((size_t)b*NN + n0)*TD);
    for (int i = tid; i < nrows*96; i += 256){
        int r = i / 96, c4 = i - r*96;
        const float* sr = stage + r*OST + c4*4;
        float w = w_s[r*TT + (c4 >> 2)];
        float4 v;
        v.x = sr[0] + w; v.y = sr[1] + w; v.z = sr[2] + w; v.w = sr[3] + w;
        outp[i] = v;
    }
}

// ============================================================
extern "C" void kernel_launch(void* const* d_in, const int* in_sizes, int n_in,
                              void* d_out, int out_size)
{
    (void)in_sizes; (void)n_in; (void)out_size;
    const float* x     = (const float*)d_in[0];
    const float* Wq    = (const float*)d_in[1];
    const float* bq    = (const float*)d_in[2];
    const float* Wk    = (const float*)d_in[3];
    const float* bk    = (const float*)d_in[4];
    const float* g0    = (const float*)d_in[5];
    const float* beta0 = (const float*)d_in[6];
    const float* g1    = (const float*)d_in[7];
    const float* beta1 = (const float*)d_in[8];
    const float* nrm   = (const float*)d_in[9];
    const float* Win   = (const float*)d_in[10];
    float* out = (float*)d_out;

    cudaFuncSetAttribute(qk_ln_kernel, cudaFuncAttributeMaxDynamicSharedMemorySize, K1_SM_BYTES);
    cudaFuncSetAttribute(attn_mma,     cudaFuncAttributeMaxDynamicSharedMemorySize, SMEM_ATT);

    prep_vt<<<(TD*NNP + 255)/256, 256>>>(nrm);
    qk_ln_kernel<<<(B*NN)/K1_ROWS, 512, K1_SM_BYTES>>>(x, Wq, bq, Wk, bk, g0, beta0, g1, beta1);

    dim3 grid((NN + BR - 1)/BR, B);
    attn_mma<<<grid, 256, SMEM_ATT>>>(x, Win, out);
}